// round 6
// baseline (speedup 1.0000x reference)
#include <cuda_runtime.h>

#define BATCH    32
#define D_IN     1024
#define D_OUT    1024
#define E_DIM    3076                    // D_OUT + 2*D_IN + 4
#define GROUP    4
#define NGROUPS  (BATCH / GROUP)         // 8
#define ROWS_G   (GROUP * E_DIM)         // 12304
#define MV_BLOCKS (ROWS_G / 8)           // 1538 (8 warps/block, 1 row/warp)
#define UPB_PER_BATCH ((E_DIM + 31) / 32) // 97
#define UP_BLOCKS (UPB_PER_BATCH * GROUP) // 388

// Scratch + sync (allocation-free rule: __device__ globals)
__device__ float    g_out [BATCH * E_DIM];
__device__ float    g_kphi[BATCH * D_IN];
__device__ float    g_qphi[BATCH * D_IN];
__device__ float    g_sig [BATCH * 4];
__device__ unsigned g_flag[NGROUPS];

__global__ void srwm_init()
{
    for (int i = 0; i < NGROUPS; i++) g_flag[i] = 0;
}

// ---------------------------------------------------------------------------
// Softmax task: task in [0,8): batch = gi*GROUP + task/2, kind = task&1.
// 256 threads, 4 elems each (float4). Task 0 also does the 16 sigmoids.
// ---------------------------------------------------------------------------
__device__ void softmax_task(int gi, int task, int tid)
{
    __shared__ float sred[8];
    __shared__ float sval;
    const int b    = gi * GROUP + (task >> 1);
    const int lane = tid & 31;
    const int warp = tid >> 5;

    const float* src = g_out + (size_t)b * E_DIM + D_OUT + (size_t)(task & 1) * D_IN;
    float4 v = ((const float4*)src)[tid];

    float m = fmaxf(fmaxf(v.x, v.y), fmaxf(v.z, v.w));
#pragma unroll
    for (int o = 16; o; o >>= 1) m = fmaxf(m, __shfl_xor_sync(0xffffffffu, m, o));
    if (lane == 0) sred[warp] = m;
    __syncthreads();
    if (tid == 0) {
        float t = sred[0];
#pragma unroll
        for (int i = 1; i < 8; i++) t = fmaxf(t, sred[i]);
        sval = t;
    }
    __syncthreads();
    m = sval;
    float e0 = __expf(v.x - m), e1 = __expf(v.y - m);
    float e2 = __expf(v.z - m), e3 = __expf(v.w - m);
    float s = e0 + e1 + e2 + e3;
#pragma unroll
    for (int o = 16; o; o >>= 1) s += __shfl_xor_sync(0xffffffffu, s, o);
    __syncthreads();
    if (lane == 0) sred[warp] = s;
    __syncthreads();
    if (tid == 0) {
        float t = 0.f;
#pragma unroll
        for (int i = 0; i < 8; i++) t += sred[i];
        sval = t;
    }
    __syncthreads();
    float inv = 1.0f / sval;
    float* dst = (task & 1) ? g_qphi : g_kphi;
    float4 o4 = {e0 * inv, e1 * inv, e2 * inv, e3 * inv};
    ((float4*)(dst + (size_t)b * D_IN))[tid] = o4;

    if (task == 0 && tid < 4 * GROUP) {
        int bb = gi * GROUP + (tid >> 2), k = tid & 3;
        float t = g_out[(size_t)bb * E_DIM + D_OUT + 2 * D_IN + k];
        g_sig[bb * 4 + k] = 1.0f / (1.0f + __expf(-t));
    }

    __threadfence();
    __syncthreads();
    if (tid == 0) atomicAdd(&g_flag[gi], 1u);
}

// ---------------------------------------------------------------------------
// Combined kernel. Block roles by blockIdx.x:
//   g_mv >= 0 : first MV_BLOCKS blocks do matvec rows of group g_mv.
//   g_up >= 0 : remaining UP_BLOCKS blocks do the update of group g_up.
// Blocks 0..7 additionally compute softmax(g_up) first (they are wave-1).
// ---------------------------------------------------------------------------
__global__ void __launch_bounds__(256)
srwm_stage(const float* __restrict__ w, const float* __restrict__ x,
           float* __restrict__ y, float* __restrict__ wout,
           int write_y, int g_mv, int g_up)
{
    const int tid  = threadIdx.x;
    const int bid  = blockIdx.x;
    const int lane = tid & 31;
    const int warp = tid >> 5;
    const int n_mv = (g_mv >= 0) ? MV_BLOCKS : 0;

    // ---- softmax for the update group, by the first 8 blocks ----
    if (g_up >= 0 && bid < 8) {
        softmax_task(g_up, bid, tid);
        __syncthreads();
    }

    if (bid < n_mv) {
        // =============== MATVEC role ===============
        const int row = bid * 8 + warp;            // < ROWS_G (exact)
        const int bi  = row / E_DIM;
        const int e   = row - bi * E_DIM;
        const int b   = g_mv * GROUP + bi;

        const float4* wrow = (const float4*)(w + ((size_t)b * E_DIM + e) * D_IN);
        const float4* x4   = (const float4*)(x + (size_t)b * D_IN);

        float acc = 0.f;
#pragma unroll
        for (int j = 0; j < 8; j++) {
            float4 wv = wrow[lane + j * 32];
            float4 xv = __ldg(x4 + lane + j * 32);
            acc += wv.x * xv.x + wv.y * xv.y + wv.z * xv.z + wv.w * xv.w;
        }
#pragma unroll
        for (int o = 16; o; o >>= 1) acc += __shfl_xor_sync(0xffffffffu, acc, o);
        if (lane == 0) {
            g_out[(size_t)b * E_DIM + e] = acc;
            if (write_y && e < D_OUT) y[(size_t)b * D_OUT + e] = acc;
        }
        return;
    }

    if (g_up < 0) return;

    // =============== UPDATE role ===============
    const int ub = bid - n_mv;                     // 0 .. UP_BLOCKS-1
    const int bi = ub / UPB_PER_BATCH;
    const int b  = g_up * GROUP + bi;
    const int e0 = (ub - bi * UPB_PER_BATCH) * 32;

    __shared__ float4 sk4[D_IN / 4];
    __shared__ float4 sq4[D_IN / 4];
    __shared__ float  ssig[4];

    // wait for softmax(g_up) (flag == 8) — producers are blocks 0..7 (wave 1)
    if (tid == 0) {
        while (*(volatile unsigned*)&g_flag[g_up] < 8u) __nanosleep(64);
    }
    __syncthreads();

    const float4* gk = (const float4*)(g_kphi + (size_t)b * D_IN);
    const float4* gq = (const float4*)(g_qphi + (size_t)b * D_IN);
    for (int i = tid; i < D_IN / 4; i += 256) {
        sk4[i] = gk[i];
        sq4[i] = gq[i];
    }
    if (tid < 4) ssig[tid] = g_sig[b * 4 + tid];
    __syncthreads();

#pragma unroll 1
    for (int r = 0; r < 4; r++) {
        const int e = e0 + warp * 4 + r;
        if (e >= E_DIM) break;

        const float4* wrow = (const float4*)(w    + ((size_t)b * E_DIM + e) * D_IN);
        float4*       orow = (float4*)      (wout + ((size_t)b * E_DIM + e) * D_IN);

        float4 wv[8];
        float av = 0.f, ab = 0.f;
#pragma unroll
        for (int j = 0; j < 8; j++) {
            wv[j] = __ldcs(wrow + lane + j * 32);
            float4 kv = sk4[lane + j * 32];
            float4 qv = sq4[lane + j * 32];
            ab += wv[j].x * kv.x + wv[j].y * kv.y + wv[j].z * kv.z + wv[j].w * kv.w;
            av += wv[j].x * qv.x + wv[j].y * qv.y + wv[j].z * qv.z + wv[j].w * qv.w;
        }
#pragma unroll
        for (int o = 16; o; o >>= 1) {
            av += __shfl_xor_sync(0xffffffffu, av, o);
            ab += __shfl_xor_sync(0xffffffffu, ab, o);
        }
        const int seg = (e < D_OUT) ? 0 : (e < D_OUT + D_IN) ? 1 :
                        (e < D_OUT + 2 * D_IN) ? 2 : 3;
        const float coeff = ssig[seg] * (av - ab);
#pragma unroll
        for (int j = 0; j < 8; j++) {
            float4 kv = sk4[lane + j * 32];
            float4 o4;
            o4.x = wv[j].x + coeff * kv.x;
            o4.y = wv[j].y + coeff * kv.y;
            o4.z = wv[j].z + coeff * kv.z;
            o4.w = wv[j].w + coeff * kv.w;
            __stcs(orow + lane + j * 32, o4);
        }
    }
}

// ---------------------------------------------------------------------------
// kernel_launch: init + 9 pipelined stage kernels (10 graph nodes).
// ---------------------------------------------------------------------------
extern "C" void kernel_launch(void* const* d_in, const int* in_sizes, int n_in,
                              void* d_out, int out_size)
{
    const float* x = (const float*)d_in[0];
    const float* w = (const float*)d_in[1];
    if (n_in >= 2 && in_sizes[0] != BATCH * D_IN) {
        x = (const float*)d_in[1];
        w = (const float*)d_in[0];
    }

    const size_t wout_elems = (size_t)BATCH * E_DIM * D_IN;
    float* out = (float*)d_out;

    float* y_ptr    = out;
    float* wout_ptr = out + ((size_t)out_size - wout_elems);
    const int write_y = ((size_t)out_size > wout_elems) ? 1 : 0;

    srwm_init<<<1, 1>>>();

    // stage 0: matvec only
    srwm_stage<<<MV_BLOCKS, 256>>>(w, x, y_ptr, wout_ptr, write_y, 0, -1);
    // stages 1..7: mv(s) + update(s-1)
    for (int s = 1; s < NGROUPS; s++)
        srwm_stage<<<MV_BLOCKS + UP_BLOCKS, 256>>>(w, x, y_ptr, wout_ptr,
                                                   write_y, s, s - 1);
    // final: update(7) only (blocks 0..7 do softmax(7) first)
    srwm_stage<<<UP_BLOCKS, 256>>>(w, x, y_ptr, wout_ptr, write_y, -1,
                                   NGROUPS - 1);
}

// round 8
// speedup vs baseline: 1.0636x; 1.0636x over previous
#include <cuda_runtime.h>

#define BATCH 32
#define D_IN  1024
#define D_OUT 1024
#define E_DIM (D_OUT + 2 * D_IN + 4)   // 3076

// Scratch (allocation-free rule: __device__ globals)
__device__ float g_out [BATCH * E_DIM];   // first matvec result
__device__ float g_kphi[BATCH * D_IN];    // softmax(k)
__device__ float g_qphi[BATCH * D_IN];    // softmax(q)
__device__ float g_sig [BATCH * 4];       // sigmoid(b1..b4)

// ---------------------------------------------------------------------------
// Kernel 1: out[b,e] = dot(w[b,e,:], x[b,:]); also writes y = out[:, :D_OUT].
// One warp per row e; 8 warps/block; x staged in shared.
// Processes batches in ASCENDING order (blockIdx.y = b); the L2 tail
// (last ~126 MB = highest batches) stays resident for the update kernel.
// ---------------------------------------------------------------------------
__global__ void __launch_bounds__(256) srwm_matvec(const float* __restrict__ w,
                                                   const float* __restrict__ x,
                                                   float* __restrict__ y_out,
                                                   int write_y)
{
    __shared__ float4 sx4[D_IN / 4];
    const int b = blockIdx.y;

    const float4* x4 = (const float4*)(x + (size_t)b * D_IN);
    for (int i = threadIdx.x; i < D_IN / 4; i += blockDim.x) sx4[i] = x4[i];
    __syncthreads();

    const int warp = threadIdx.x >> 5;
    const int lane = threadIdx.x & 31;
    const int e = blockIdx.x * 8 + warp;
    if (e >= E_DIM) return;

    const float4* wrow = (const float4*)(w + ((size_t)b * E_DIM + e) * D_IN);

    float acc = 0.0f;
#pragma unroll
    for (int j = 0; j < 8; j++) {
        float4 wv = wrow[lane + j * 32];
        float4 xv = sx4[lane + j * 32];
        acc += wv.x * xv.x + wv.y * xv.y + wv.z * xv.z + wv.w * xv.w;
    }
#pragma unroll
    for (int off = 16; off; off >>= 1)
        acc += __shfl_xor_sync(0xffffffffu, acc, off);

    if (lane == 0) {
        g_out[(size_t)b * E_DIM + e] = acc;
        if (write_y && e < D_OUT) y_out[(size_t)b * D_OUT + e] = acc;
    }
}

// ---------------------------------------------------------------------------
// Kernel 2: per-batch softmax of k and q rows, plus 4 sigmoids. 32 blocks.
// ---------------------------------------------------------------------------
__global__ void __launch_bounds__(256) srwm_softmax()
{
    const int b    = blockIdx.x;
    const int tid  = threadIdx.x;
    const int lane = tid & 31;
    const int warp = tid >> 5;

    __shared__ float sred[8];
    __shared__ float sval;

    const float* base = g_out + (size_t)b * E_DIM;

    // ---- K softmax ----
    {
        float4 v = ((const float4*)(base + D_OUT))[tid];
        float m = fmaxf(fmaxf(v.x, v.y), fmaxf(v.z, v.w));
#pragma unroll
        for (int off = 16; off; off >>= 1)
            m = fmaxf(m, __shfl_xor_sync(0xffffffffu, m, off));
        if (lane == 0) sred[warp] = m;
        __syncthreads();
        if (tid == 0) {
            float t = sred[0];
#pragma unroll
            for (int i = 1; i < 8; i++) t = fmaxf(t, sred[i]);
            sval = t;
        }
        __syncthreads();
        m = sval;
        float e0 = __expf(v.x - m), e1 = __expf(v.y - m);
        float e2 = __expf(v.z - m), e3 = __expf(v.w - m);
        float s = e0 + e1 + e2 + e3;
#pragma unroll
        for (int off = 16; off; off >>= 1)
            s += __shfl_xor_sync(0xffffffffu, s, off);
        __syncthreads();
        if (lane == 0) sred[warp] = s;
        __syncthreads();
        if (tid == 0) {
            float t = 0.0f;
#pragma unroll
            for (int i = 0; i < 8; i++) t += sred[i];
            sval = t;
        }
        __syncthreads();
        float inv = 1.0f / sval;
        float4 o = {e0 * inv, e1 * inv, e2 * inv, e3 * inv};
        ((float4*)(g_kphi + (size_t)b * D_IN))[tid] = o;
        __syncthreads();
    }

    // ---- Q softmax ----
    {
        float4 v = ((const float4*)(base + D_OUT + D_IN))[tid];
        float m = fmaxf(fmaxf(v.x, v.y), fmaxf(v.z, v.w));
#pragma unroll
        for (int off = 16; off; off >>= 1)
            m = fmaxf(m, __shfl_xor_sync(0xffffffffu, m, off));
        if (lane == 0) sred[warp] = m;
        __syncthreads();
        if (tid == 0) {
            float t = sred[0];
#pragma unroll
            for (int i = 1; i < 8; i++) t = fmaxf(t, sred[i]);
            sval = t;
        }
        __syncthreads();
        m = sval;
        float e0 = __expf(v.x - m), e1 = __expf(v.y - m);
        float e2 = __expf(v.z - m), e3 = __expf(v.w - m);
        float s = e0 + e1 + e2 + e3;
#pragma unroll
        for (int off = 16; off; off >>= 1)
            s += __shfl_xor_sync(0xffffffffu, s, off);
        __syncthreads();
        if (lane == 0) sred[warp] = s;
        __syncthreads();
        if (tid == 0) {
            float t = 0.0f;
#pragma unroll
            for (int i = 0; i < 8; i++) t += sred[i];
            sval = t;
        }
        __syncthreads();
        float inv = 1.0f / sval;
        float4 o = {e0 * inv, e1 * inv, e2 * inv, e3 * inv};
        ((float4*)(g_qphi + (size_t)b * D_IN))[tid] = o;
    }

    // ---- sigmoids of the 4 bias outputs ----
    if (tid < 4) {
        float v = base[D_OUT + 2 * D_IN + tid];
        g_sig[b * 4 + tid] = 1.0f / (1.0f + __expf(-v));
    }
}

// ---------------------------------------------------------------------------
// Kernel 3: fused vbar/v matvecs + rank-1 update, REVERSED iteration order.
// Block (x,y) maps to batch = 31 - y, row chunk = nchunks-1 - x, so the first
// blocks scheduled touch the w lines most recently read by the matvec kernel
// (still L2-resident). w read __ldcs (last use), wout written __stcs.
// ---------------------------------------------------------------------------
__global__ void __launch_bounds__(256) srwm_update(const float* __restrict__ w,
                                                   float* __restrict__ wout)
{
    __shared__ float4 sk4[D_IN / 4];
    __shared__ float4 sq4[D_IN / 4];
    __shared__ float  ssig[4];

    // reversed mapping
    const int b = (BATCH - 1) - blockIdx.y;
    const int chunk = (gridDim.x - 1) - blockIdx.x;

    const float4* gk = (const float4*)(g_kphi + (size_t)b * D_IN);
    const float4* gq = (const float4*)(g_qphi + (size_t)b * D_IN);
    for (int i = threadIdx.x; i < D_IN / 4; i += blockDim.x) {
        sk4[i] = gk[i];
        sq4[i] = gq[i];
    }
    if (threadIdx.x < 4) ssig[threadIdx.x] = g_sig[b * 4 + threadIdx.x];
    __syncthreads();

    const int warp = threadIdx.x >> 5;
    const int lane = threadIdx.x & 31;
    const int e_base = chunk * 32 + warp * 4;

#pragma unroll 1
    for (int r = 3; r >= 0; r--) {      // reversed within warp's 4 rows
        const int e = e_base + r;
        if (e >= E_DIM) continue;

        const float4* wrow = (const float4*)(w    + ((size_t)b * E_DIM + e) * D_IN);
        float4*       orow = (float4*)      (wout + ((size_t)b * E_DIM + e) * D_IN);

        float4 wv[8];
        float acc_v = 0.0f, acc_vb = 0.0f;
#pragma unroll
        for (int j = 0; j < 8; j++) {
            wv[j] = __ldcs(&wrow[lane + j * 32]);
            float4 kv = sk4[lane + j * 32];
            float4 qv = sq4[lane + j * 32];
            acc_vb += wv[j].x * kv.x + wv[j].y * kv.y + wv[j].z * kv.z + wv[j].w * kv.w;
            acc_v  += wv[j].x * qv.x + wv[j].y * qv.y + wv[j].z * qv.z + wv[j].w * qv.w;
        }
#pragma unroll
        for (int off = 16; off; off >>= 1) {
            acc_v  += __shfl_xor_sync(0xffffffffu, acc_v,  off);
            acc_vb += __shfl_xor_sync(0xffffffffu, acc_vb, off);
        }

        const int seg = (e < D_OUT) ? 0 : (e < D_OUT + D_IN) ? 1 :
                        (e < D_OUT + 2 * D_IN) ? 2 : 3;
        const float coeff = ssig[seg] * (acc_v - acc_vb);

#pragma unroll
        for (int j = 0; j < 8; j++) {
            float4 kv = sk4[lane + j * 32];
            float4 o;
            o.x = wv[j].x + coeff * kv.x;
            o.y = wv[j].y + coeff * kv.y;
            o.z = wv[j].z + coeff * kv.z;
            o.w = wv[j].w + coeff * kv.w;
            __stcs(&orow[lane + j * 32], o);
        }
    }
}

// ---------------------------------------------------------------------------
// kernel_launch
// ---------------------------------------------------------------------------
extern "C" void kernel_launch(void* const* d_in, const int* in_sizes, int n_in,
                              void* d_out, int out_size)
{
    const float* x = (const float*)d_in[0];
    const float* w = (const float*)d_in[1];
    if (n_in >= 2 && in_sizes[0] != BATCH * D_IN) {
        x = (const float*)d_in[1];
        w = (const float*)d_in[0];
    }

    const size_t wout_elems = (size_t)BATCH * E_DIM * D_IN;
    float* out = (float*)d_out;

    float* y_ptr = out;
    float* wout_ptr = out + ((size_t)out_size - wout_elems);
    const int write_y = ((size_t)out_size > wout_elems) ? 1 : 0;

    dim3 grid1((E_DIM + 7) / 8, BATCH);
    srwm_matvec<<<grid1, 256>>>(w, x, y_ptr, write_y);

    srwm_softmax<<<BATCH, 256>>>();

    dim3 grid3((E_DIM + 31) / 32, BATCH);
    srwm_update<<<grid3, 256>>>(w, wout_ptr);
}